// round 9
// baseline (speedup 1.0000x reference)
#include <cuda_runtime.h>
#include <cuda_fp16.h>

#define NUx 200000
#define NIx 100000
#define Dx  64
#define Ex  2000000
#define Bx  8192
#define EPSx 1e-12f

#define SB 256
#define SI 8                 // 2048 elements per scan block
#define NW (SB/32)

// ---- static device scratch (no allocation allowed) ----
__device__ int g_deg_u[NUx];
__device__ int g_deg_i[NIx];
__device__ int g_off_u[NUx];
__device__ int g_off_i[NIx];
__device__ int g_cur_u[NUx];
__device__ int g_cur_i[NIx];
__device__ int g_bsum_u[128];
__device__ int g_bsum_i[128];
__device__ __align__(16) int2 g_adj_u[Ex];   // per-user: (item, norm_e)
__device__ __align__(16) int2 g_adj_i[Ex];   // per-item: (user, norm_e)

// fp16 feature storage: rows of 32 half2 (64 halves = 128B)
__device__ __align__(256) __half2 g_uf16[(size_t)NUx * 32];
__device__ __align__(256) __half2 g_if16[(size_t)NIx * 32];
__device__ __align__(256) __half2 g_hu16[3][(size_t)NUx * 32];
__device__ __align__(256) __half2 g_hi16[3][(size_t)NIx * 32];

// ---- degree histogram (int) ----
__global__ void k_deg(const int* __restrict__ eu, const int* __restrict__ ei) {
    int t = blockIdx.x * blockDim.x + threadIdx.x;
    if (t < Ex) {
        atomicAdd(&g_deg_u[eu[t]], 1);
        atomicAdd(&g_deg_i[ei[t]], 1);
    }
}

// ---- exclusive scan, stage 1: per-block scan + block sums ----
__global__ void k_scan_blocks(const int* __restrict__ in, int* __restrict__ out,
                              int* __restrict__ bsum, int n) {
    __shared__ int warp_tot[NW];
    int lane = threadIdx.x & 31, wid = threadIdx.x >> 5;
    int base = blockIdx.x * (SB * SI) + threadIdx.x * SI;

    int v[SI];
    int s = 0;
    #pragma unroll
    for (int k = 0; k < SI; ++k) {
        int idx = base + k;
        v[k] = (idx < n) ? in[idx] : 0;
        s += v[k];
    }
    int ps = s;
    #pragma unroll
    for (int o = 1; o < 32; o <<= 1) {
        int t = __shfl_up_sync(0xffffffffu, ps, o);
        if (lane >= o) ps += t;
    }
    if (lane == 31) warp_tot[wid] = ps;
    __syncthreads();
    if (wid == 0) {
        int wt = (lane < NW) ? warp_tot[lane] : 0;
        int wps = wt;
        #pragma unroll
        for (int o = 1; o < NW; o <<= 1) {
            int t = __shfl_up_sync(0xffffffffu, wps, o);
            if (lane >= o) wps += t;
        }
        if (lane < NW) warp_tot[lane] = wps - wt;
    }
    __syncthreads();
    int excl = warp_tot[wid] + (ps - s);
    int run = excl;
    #pragma unroll
    for (int k = 0; k < SI; ++k) {
        int idx = base + k;
        if (idx < n) out[idx] = run;
        run += v[k];
    }
    if (threadIdx.x == SB - 1) bsum[blockIdx.x] = excl + s;
}

// ---- exclusive scan of both block-sum arrays in one launch ----
__global__ void k_scan_small2(int* __restrict__ bu, int nu_,
                              int* __restrict__ bi, int ni_) {
    int* b = blockIdx.x ? bi : bu;
    int n  = blockIdx.x ? ni_ : nu_;
    __shared__ int wt[4];
    int tid = threadIdx.x;
    int lane = tid & 31, wid = tid >> 5;
    int v = (tid < n) ? b[tid] : 0;
    int ps = v;
    #pragma unroll
    for (int o = 1; o < 32; o <<= 1) {
        int t = __shfl_up_sync(0xffffffffu, ps, o);
        if (lane >= o) ps += t;
    }
    if (lane == 31) wt[wid] = ps;
    __syncthreads();
    if (tid == 0) {
        int r = 0;
        #pragma unroll
        for (int k = 0; k < 4; ++k) { int t = wt[k]; wt[k] = r; r += t; }
    }
    __syncthreads();
    if (tid < n) b[tid] = wt[wid] + ps - v;
}

// ---- scan stage 3: add block offsets; also init cursor copy ----
__global__ void k_scan_add(int* __restrict__ out, int* __restrict__ cur,
                           const int* __restrict__ bsum, int n) {
    int base = blockIdx.x * (SB * SI) + threadIdx.x * SI;
    int add = bsum[blockIdx.x];
    #pragma unroll
    for (int k = 0; k < SI; ++k) {
        int idx = base + k;
        if (idx < n) {
            int val = out[idx] + add;
            out[idx] = val;
            cur[idx] = val;
        }
    }
}

// ---- counting-sort fill of both adjacency lists + per-edge norm ----
__global__ void k_fill(const int* __restrict__ eu, const int* __restrict__ ei) {
    int e = blockIdx.x * blockDim.x + threadIdx.x;
    if (e >= Ex) return;
    int u = eu[e], i = ei[e];
    float w = rsqrtf((float)(g_deg_u[u] * g_deg_i[i]));
    int wb = __float_as_int(w);
    int pu = atomicAdd(&g_cur_u[u], 1);
    g_adj_u[pu] = make_int2(i, wb);
    int pi = atomicAdd(&g_cur_i[i], 1);
    g_adj_i[pi] = make_int2(u, wb);
}

// ---- convert fp32 inputs to fp16 staging ----
__global__ void k_cvt(const float* __restrict__ uf, const float* __restrict__ itf) {
    int t = blockIdx.x * blockDim.x + threadIdx.x;
    if (t < NUx * 32) {
        float2 f = ((const float2*)uf)[t];
        g_uf16[t] = __float22half2_rn(f);
    } else if (t < (NUx + NIx) * 32) {
        int s = t - NUx * 32;
        float2 f = ((const float2*)itf)[s];
        g_if16[s] = __float22half2_rn(f);
    }
}

// ---- merged both-direction gather-aggregate + fused L2-normalize ----
// ONE WARP PER FOUR CONSECUTIVE DEST ROWS. Their CSR ranges are adjacent, so
// the warp stages [off[4k], off[4k+4]) as one contiguous stream; the row-select
// compares are warp-uniform (j comes from a shared broadcast). Amortizes
// offset loads, staging waits, and epilogue over 4 rows; 4 independent
// accumulator chains raise MLP.
__global__ void k_agg(const __half2* __restrict__ srcU,
                      const __half2* __restrict__ srcI,
                      __half2* __restrict__ houtU,
                      __half2* __restrict__ houtI) {
    __shared__ int2 sh[NW][32];
    int gw = (blockIdx.x * blockDim.x + threadIdx.x) >> 5;   // quad index
    int lane = threadIdx.x & 31;
    int wid = threadIdx.x >> 5;
    const int QI = NIx / 4, QU = NUx / 4;
    if (gw >= QI + QU) return;

    const __half2* src;
    __half2* hout;
    const int2* adj;
    const int* off;
    int row0, nrows;
    if (gw < QI) {
        row0 = gw * 4; nrows = NIx;
        src = srcU; hout = houtI; adj = g_adj_i; off = g_off_i;
    } else {
        row0 = (gw - QI) * 4; nrows = NUx;
        src = srcI; hout = houtU; adj = g_adj_u; off = g_off_u;
    }

    int beg = off[row0];
    int b1  = off[row0 + 1];
    int b2  = off[row0 + 2];
    int b3  = off[row0 + 3];
    int end = (row0 + 4 < nrows) ? off[row0 + 4] : Ex;

    float2 acc0 = make_float2(0.f, 0.f);
    float2 acc1 = make_float2(0.f, 0.f);
    float2 acc2 = make_float2(0.f, 0.f);
    float2 acc3 = make_float2(0.f, 0.f);

    for (int p = beg; p < end; p += 32) {
        int idx = p + lane;
        if (idx < end) sh[wid][lane] = adj[idx];
        __syncwarp();
        int c = min(end - p, 32);
        #pragma unroll 4
        for (int j = 0; j < c; ++j) {
            int2 a = sh[wid][j];
            float2 v = __half22float2(src[(size_t)a.x * 32 + lane]);
            float w = __int_as_float(a.y);
            int t = p + j;                     // warp-uniform
            if (t < b2) {
                if (t < b1) { acc0.x += w * v.x; acc0.y += w * v.y; }
                else        { acc1.x += w * v.x; acc1.y += w * v.y; }
            } else {
                if (t < b3) { acc2.x += w * v.x; acc2.y += w * v.y; }
                else        { acc3.x += w * v.x; acc3.y += w * v.y; }
            }
        }
        __syncwarp();
    }

    float s0 = acc0.x * acc0.x + acc0.y * acc0.y;
    float s1 = acc1.x * acc1.x + acc1.y * acc1.y;
    float s2 = acc2.x * acc2.x + acc2.y * acc2.y;
    float s3 = acc3.x * acc3.x + acc3.y * acc3.y;
    #pragma unroll
    for (int o = 16; o; o >>= 1) {
        s0 += __shfl_xor_sync(0xffffffffu, s0, o);
        s1 += __shfl_xor_sync(0xffffffffu, s1, o);
        s2 += __shfl_xor_sync(0xffffffffu, s2, o);
        s3 += __shfl_xor_sync(0xffffffffu, s3, o);
    }
    float inv0 = 1.0f / fmaxf(sqrtf(s0), EPSx);
    float inv1 = 1.0f / fmaxf(sqrtf(s1), EPSx);
    float inv2 = 1.0f / fmaxf(sqrtf(s2), EPSx);
    float inv3 = 1.0f / fmaxf(sqrtf(s3), EPSx);

    hout[(size_t)row0 * 32 + lane] =
        __float22half2_rn(make_float2(acc0.x * inv0, acc0.y * inv0));
    hout[(size_t)(row0 + 1) * 32 + lane] =
        __float22half2_rn(make_float2(acc1.x * inv1, acc1.y * inv1));
    hout[(size_t)(row0 + 2) * 32 + lane] =
        __float22half2_rn(make_float2(acc2.x * inv2, acc2.y * inv2));
    hout[(size_t)(row0 + 3) * 32 + lane] =
        __float22half2_rn(make_float2(acc3.x * inv3, acc3.y * inv3));
}

// ---- final gather: e = f + h0 + h1/2 + h2/3 at sampled rows ----
__global__ void k_out(const float* __restrict__ uf, const float* __restrict__ itf,
                      const int* __restrict__ users, const int* __restrict__ pos,
                      const int* __restrict__ neg, float* __restrict__ out) {
    unsigned t = blockIdx.x * blockDim.x + threadIdx.x;
    unsigned r = t >> 4;
    unsigned lane = t & 15u;          // 16 lanes x 4 cols = 64
    if (r >= 3u * Bx) return;
    unsigned grp = r / Bx, idx = r % Bx;

    const float* base;
    const __half2 *h0, *h1, *h2;
    size_t row;
    if (grp == 0) {
        row = (size_t)users[idx];
        base = uf + row * Dx;
        h0 = g_hu16[0] + row * 32; h1 = g_hu16[1] + row * 32; h2 = g_hu16[2] + row * 32;
    } else {
        row = (size_t)((grp == 1) ? pos[idx] : neg[idx]);
        base = itf + row * Dx;
        h0 = g_hi16[0] + row * 32; h1 = g_hi16[1] + row * 32; h2 = g_hi16[2] + row * 32;
    }

    float4 f = *(const float4*)(base + lane * 4);
    float2 a0 = __half22float2(h0[lane * 2]), b0 = __half22float2(h0[lane * 2 + 1]);
    float2 a1 = __half22float2(h1[lane * 2]), b1 = __half22float2(h1[lane * 2 + 1]);
    float2 a2 = __half22float2(h2[lane * 2]), b2 = __half22float2(h2[lane * 2 + 1]);

    const float c1 = 0.5f, c2 = 1.0f / 3.0f;
    f.x += a0.x + c1 * a1.x + c2 * a2.x;
    f.y += a0.y + c1 * a1.y + c2 * a2.y;
    f.z += b0.x + c1 * b1.x + c2 * b2.x;
    f.w += b0.y + c1 * b1.y + c2 * b2.y;

    *(float4*)(out + (size_t)r * Dx + lane * 4) = f;
}

extern "C" void kernel_launch(void* const* d_in, const int* in_sizes, int n_in,
                              void* d_out, int out_size) {
    const float* uf  = (const float*)d_in[0];
    const float* itf = (const float*)d_in[1];
    const int*   eu  = (const int*)d_in[2];
    const int*   ei  = (const int*)d_in[3];
    const int*   usr = (const int*)d_in[4];
    const int*   pos = (const int*)d_in[5];
    const int*   neg = (const int*)d_in[6];
    float* out = (float*)d_out;

    void *p_deg_u, *p_deg_i, *p_off_u, *p_off_i, *p_cur_u, *p_cur_i;
    void *p_bsum_u, *p_bsum_i;
    void *p_uf16, *p_if16, *p_hu[3], *p_hi[3];
    cudaGetSymbolAddress(&p_deg_u, g_deg_u);
    cudaGetSymbolAddress(&p_deg_i, g_deg_i);
    cudaGetSymbolAddress(&p_off_u, g_off_u);
    cudaGetSymbolAddress(&p_off_i, g_off_i);
    cudaGetSymbolAddress(&p_cur_u, g_cur_u);
    cudaGetSymbolAddress(&p_cur_i, g_cur_i);
    cudaGetSymbolAddress(&p_bsum_u, g_bsum_u);
    cudaGetSymbolAddress(&p_bsum_i, g_bsum_i);
    cudaGetSymbolAddress(&p_uf16, g_uf16);
    cudaGetSymbolAddress(&p_if16, g_if16);
    {
        void* tmp;
        cudaGetSymbolAddress(&tmp, g_hu16);
        for (int k = 0; k < 3; ++k) p_hu[k] = (char*)tmp + (size_t)k * NUx * 32 * sizeof(__half2);
        cudaGetSymbolAddress(&tmp, g_hi16);
        for (int k = 0; k < 3; ++k) p_hi[k] = (char*)tmp + (size_t)k * NIx * 32 * sizeof(__half2);
    }

    const int scanb_u = (NUx + SB * SI - 1) / (SB * SI);   // 98
    const int scanb_i = (NIx + SB * SI - 1) / (SB * SI);   // 49

    // ---- CSR build + fp16 input staging ----
    cudaMemsetAsync(p_deg_u, 0, NUx * sizeof(int));
    cudaMemsetAsync(p_deg_i, 0, NIx * sizeof(int));
    k_deg<<<(Ex + 255) / 256, 256>>>(eu, ei);
    k_cvt<<<((NUx + NIx) * 32 + 255) / 256, 256>>>(uf, itf);
    k_scan_blocks<<<scanb_u, SB>>>((const int*)p_deg_u, (int*)p_off_u, (int*)p_bsum_u, NUx);
    k_scan_blocks<<<scanb_i, SB>>>((const int*)p_deg_i, (int*)p_off_i, (int*)p_bsum_i, NIx);
    k_scan_small2<<<2, 128>>>((int*)p_bsum_u, scanb_u, (int*)p_bsum_i, scanb_i);
    k_scan_add<<<scanb_u, SB>>>((int*)p_off_u, (int*)p_cur_u, (const int*)p_bsum_u, NUx);
    k_scan_add<<<scanb_i, SB>>>((int*)p_off_i, (int*)p_cur_i, (const int*)p_bsum_i, NIx);
    k_fill<<<(Ex + 255) / 256, 256>>>(eu, ei);

    const unsigned nquads = (NUx + NIx) / 4;
    const unsigned gagg = (unsigned)(((size_t)nquads * 32 + 255) / 256);

    // ---- 3 propagation layers (both directions merged per launch) ----
    k_agg<<<gagg, 256>>>((const __half2*)p_uf16, (const __half2*)p_if16,
                         (__half2*)p_hu[0], (__half2*)p_hi[0]);
    k_agg<<<gagg, 256>>>((const __half2*)p_hu[0], (const __half2*)p_hi[0],
                         (__half2*)p_hu[1], (__half2*)p_hi[1]);
    k_agg<<<gagg, 256>>>((const __half2*)p_hu[1], (const __half2*)p_hi[1],
                         (__half2*)p_hu[2], (__half2*)p_hi[2]);

    // ---- output gather (e computed on the fly) ----
    k_out<<<(3 * Bx * 16 + 255) / 256, 256>>>(uf, itf, usr, pos, neg, out);
}

// round 10
// speedup vs baseline: 1.5473x; 1.5473x over previous
#include <cuda_runtime.h>
#include <cuda_fp16.h>

#define NUx 200000
#define NIx 100000
#define Dx  64
#define Ex  2000000
#define Bx  8192
#define EPSx 1e-12f

#define SB 256
#define SI 8                 // 2048 elements per scan block
#define NW (SB/32)

#define CVTB (((NUx + NIx) * 32 + 255) / 256)   // 37500 blocks for cvt
#define DEGB ((Ex + 255) / 256)                 // 7813 blocks for deg
#define SCANB_U ((NUx + SB * SI - 1) / (SB * SI))   // 98
#define SCANB_I ((NIx + SB * SI - 1) / (SB * SI))   // 49

// ---- static device scratch (no allocation allowed) ----
__device__ int g_deg_u[NUx];
__device__ int g_deg_i[NIx];
__device__ int g_off_u[NUx];
__device__ int g_off_i[NIx];
__device__ int g_cur_u[NUx];
__device__ int g_cur_i[NIx];
__device__ int g_bsum_u[128];
__device__ int g_bsum_i[128];
__device__ __align__(16) int2 g_adj_u[Ex];   // per-user: (item, norm_e)
__device__ __align__(16) int2 g_adj_i[Ex];   // per-item: (user, norm_e)

// fp16 feature storage: rows of 32 half2 (64 halves = 128B)
__device__ __align__(256) __half2 g_uf16[(size_t)NUx * 32];
__device__ __align__(256) __half2 g_if16[(size_t)NIx * 32];
__device__ __align__(256) __half2 g_hu16[3][(size_t)NUx * 32];
__device__ __align__(256) __half2 g_hi16[3][(size_t)NIx * 32];

// ---- fused: fp16 input conversion + degree histogram (block-range split) ----
__global__ void k_prep(const float* __restrict__ uf, const float* __restrict__ itf,
                       const int* __restrict__ eu, const int* __restrict__ ei) {
    if (blockIdx.x < CVTB) {
        int t = blockIdx.x * blockDim.x + threadIdx.x;
        if (t < NUx * 32) {
            float2 f = ((const float2*)uf)[t];
            g_uf16[t] = __float22half2_rn(f);
        } else if (t < (NUx + NIx) * 32) {
            int s = t - NUx * 32;
            float2 f = ((const float2*)itf)[s];
            g_if16[s] = __float22half2_rn(f);
        }
    } else {
        int e = (blockIdx.x - CVTB) * blockDim.x + threadIdx.x;
        if (e < Ex) {
            atomicAdd(&g_deg_u[eu[e]], 1);
            atomicAdd(&g_deg_i[ei[e]], 1);
        }
    }
}

// ---- exclusive scan stage 1 for BOTH arrays in one launch ----
__global__ void k_scan_blocks2() {
    const int* in; int* out; int* bsum; int n; int blk;
    if (blockIdx.x < SCANB_U) {
        in = g_deg_u; out = g_off_u; bsum = g_bsum_u; n = NUx; blk = blockIdx.x;
    } else {
        in = g_deg_i; out = g_off_i; bsum = g_bsum_i; n = NIx; blk = blockIdx.x - SCANB_U;
    }
    __shared__ int warp_tot[NW];
    int lane = threadIdx.x & 31, wid = threadIdx.x >> 5;
    int base = blk * (SB * SI) + threadIdx.x * SI;

    int v[SI];
    int s = 0;
    #pragma unroll
    for (int k = 0; k < SI; ++k) {
        int idx = base + k;
        v[k] = (idx < n) ? in[idx] : 0;
        s += v[k];
    }
    int ps = s;
    #pragma unroll
    for (int o = 1; o < 32; o <<= 1) {
        int t = __shfl_up_sync(0xffffffffu, ps, o);
        if (lane >= o) ps += t;
    }
    if (lane == 31) warp_tot[wid] = ps;
    __syncthreads();
    if (wid == 0) {
        int wt = (lane < NW) ? warp_tot[lane] : 0;
        int wps = wt;
        #pragma unroll
        for (int o = 1; o < NW; o <<= 1) {
            int t = __shfl_up_sync(0xffffffffu, wps, o);
            if (lane >= o) wps += t;
        }
        if (lane < NW) warp_tot[lane] = wps - wt;
    }
    __syncthreads();
    int excl = warp_tot[wid] + (ps - s);
    int run = excl;
    #pragma unroll
    for (int k = 0; k < SI; ++k) {
        int idx = base + k;
        if (idx < n) out[idx] = run;
        run += v[k];
    }
    if (threadIdx.x == SB - 1) bsum[blk] = excl + s;
}

// ---- exclusive scan of both block-sum arrays in one launch ----
__global__ void k_scan_small2() {
    int* b = blockIdx.x ? g_bsum_i : g_bsum_u;
    int n  = blockIdx.x ? SCANB_I : SCANB_U;
    __shared__ int wt[4];
    int tid = threadIdx.x;
    int lane = tid & 31, wid = tid >> 5;
    int v = (tid < n) ? b[tid] : 0;
    int ps = v;
    #pragma unroll
    for (int o = 1; o < 32; o <<= 1) {
        int t = __shfl_up_sync(0xffffffffu, ps, o);
        if (lane >= o) ps += t;
    }
    if (lane == 31) wt[wid] = ps;
    __syncthreads();
    if (tid == 0) {
        int r = 0;
        #pragma unroll
        for (int k = 0; k < 4; ++k) { int t = wt[k]; wt[k] = r; r += t; }
    }
    __syncthreads();
    if (tid < n) b[tid] = wt[wid] + ps - v;
}

// ---- scan stage 3 for BOTH arrays in one launch; also init cursor copy ----
__global__ void k_scan_add2() {
    int* out; int* cur; const int* bsum; int n; int blk;
    if (blockIdx.x < SCANB_U) {
        out = g_off_u; cur = g_cur_u; bsum = g_bsum_u; n = NUx; blk = blockIdx.x;
    } else {
        out = g_off_i; cur = g_cur_i; bsum = g_bsum_i; n = NIx; blk = blockIdx.x - SCANB_U;
    }
    int base = blk * (SB * SI) + threadIdx.x * SI;
    int add = bsum[blk];
    #pragma unroll
    for (int k = 0; k < SI; ++k) {
        int idx = base + k;
        if (idx < n) {
            int val = out[idx] + add;
            out[idx] = val;
            cur[idx] = val;
        }
    }
}

// ---- counting-sort fill of both adjacency lists + per-edge norm ----
__global__ void k_fill(const int* __restrict__ eu, const int* __restrict__ ei) {
    int e = blockIdx.x * blockDim.x + threadIdx.x;
    if (e >= Ex) return;
    int u = eu[e], i = ei[e];
    float w = rsqrtf((float)(g_deg_u[u] * g_deg_i[i]));
    int wb = __float_as_int(w);
    int pu = atomicAdd(&g_cur_u[u], 1);
    g_adj_u[pu] = make_int2(i, wb);
    int pi = atomicAdd(&g_cur_i[i], 1);
    g_adj_i[pi] = make_int2(u, wb);
}

// ---- merged both-direction gather-aggregate + fused L2-normalize ----
// ONE WARP PER TWO CONSECUTIVE DEST ROWS (proven fastest shape, R8).
__global__ void k_agg(const __half2* __restrict__ srcU,
                      const __half2* __restrict__ srcI,
                      __half2* __restrict__ houtU,
                      __half2* __restrict__ houtI) {
    __shared__ int2 sh[NW][32];
    int gw = (blockIdx.x * blockDim.x + threadIdx.x) >> 5;   // pair index
    int lane = threadIdx.x & 31;
    int wid = threadIdx.x >> 5;
    const int PI = NIx / 2, PU = NUx / 2;
    if (gw >= PI + PU) return;

    const __half2* src;
    __half2* hout;
    const int2* adj;
    const int* off;
    int row0, nrows;
    if (gw < PI) {
        row0 = gw * 2; nrows = NIx;
        src = srcU; hout = houtI; adj = g_adj_i; off = g_off_i;
    } else {
        row0 = (gw - PI) * 2; nrows = NUx;
        src = srcI; hout = houtU; adj = g_adj_u; off = g_off_u;
    }

    int beg = off[row0];
    int mid = off[row0 + 1];
    int end = (row0 + 2 < nrows) ? off[row0 + 2] : Ex;

    float2 acc0 = make_float2(0.f, 0.f);
    float2 acc1 = make_float2(0.f, 0.f);

    for (int p = beg; p < end; p += 32) {
        int idx = p + lane;
        if (idx < end) sh[wid][lane] = adj[idx];
        __syncwarp();
        int c = min(end - p, 32);
        #pragma unroll 4
        for (int j = 0; j < c; ++j) {
            int2 a = sh[wid][j];
            float2 v = __half22float2(src[(size_t)a.x * 32 + lane]);
            float w = __int_as_float(a.y);
            if (p + j < mid) {                 // warp-uniform branch
                acc0.x += w * v.x; acc0.y += w * v.y;
            } else {
                acc1.x += w * v.x; acc1.y += w * v.y;
            }
        }
        __syncwarp();
    }

    float s0 = acc0.x * acc0.x + acc0.y * acc0.y;
    float s1 = acc1.x * acc1.x + acc1.y * acc1.y;
    #pragma unroll
    for (int o = 16; o; o >>= 1) {
        s0 += __shfl_xor_sync(0xffffffffu, s0, o);
        s1 += __shfl_xor_sync(0xffffffffu, s1, o);
    }
    float inv0 = 1.0f / fmaxf(sqrtf(s0), EPSx);
    float inv1 = 1.0f / fmaxf(sqrtf(s1), EPSx);

    hout[(size_t)row0 * 32 + lane] =
        __float22half2_rn(make_float2(acc0.x * inv0, acc0.y * inv0));
    hout[(size_t)(row0 + 1) * 32 + lane] =
        __float22half2_rn(make_float2(acc1.x * inv1, acc1.y * inv1));
}

// ---- final gather: e = f + h0 + h1/2 + h2/3 at sampled rows ----
__global__ void k_out(const float* __restrict__ uf, const float* __restrict__ itf,
                      const int* __restrict__ users, const int* __restrict__ pos,
                      const int* __restrict__ neg, float* __restrict__ out) {
    unsigned t = blockIdx.x * blockDim.x + threadIdx.x;
    unsigned r = t >> 4;
    unsigned lane = t & 15u;          // 16 lanes x 4 cols = 64
    if (r >= 3u * Bx) return;
    unsigned grp = r / Bx, idx = r % Bx;

    const float* base;
    const __half2 *h0, *h1, *h2;
    size_t row;
    if (grp == 0) {
        row = (size_t)users[idx];
        base = uf + row * Dx;
        h0 = g_hu16[0] + row * 32; h1 = g_hu16[1] + row * 32; h2 = g_hu16[2] + row * 32;
    } else {
        row = (size_t)((grp == 1) ? pos[idx] : neg[idx]);
        base = itf + row * Dx;
        h0 = g_hi16[0] + row * 32; h1 = g_hi16[1] + row * 32; h2 = g_hi16[2] + row * 32;
    }

    float4 f = *(const float4*)(base + lane * 4);
    float2 a0 = __half22float2(h0[lane * 2]), b0 = __half22float2(h0[lane * 2 + 1]);
    float2 a1 = __half22float2(h1[lane * 2]), b1 = __half22float2(h1[lane * 2 + 1]);
    float2 a2 = __half22float2(h2[lane * 2]), b2 = __half22float2(h2[lane * 2 + 1]);

    const float c1 = 0.5f, c2 = 1.0f / 3.0f;
    f.x += a0.x + c1 * a1.x + c2 * a2.x;
    f.y += a0.y + c1 * a1.y + c2 * a2.y;
    f.z += b0.x + c1 * b1.x + c2 * b2.x;
    f.w += b0.y + c1 * b1.y + c2 * b2.y;

    *(float4*)(out + (size_t)r * Dx + lane * 4) = f;
}

extern "C" void kernel_launch(void* const* d_in, const int* in_sizes, int n_in,
                              void* d_out, int out_size) {
    const float* uf  = (const float*)d_in[0];
    const float* itf = (const float*)d_in[1];
    const int*   eu  = (const int*)d_in[2];
    const int*   ei  = (const int*)d_in[3];
    const int*   usr = (const int*)d_in[4];
    const int*   pos = (const int*)d_in[5];
    const int*   neg = (const int*)d_in[6];
    float* out = (float*)d_out;

    void *p_deg_u, *p_deg_i;
    void *p_uf16, *p_if16, *p_hu[3], *p_hi[3];
    cudaGetSymbolAddress(&p_deg_u, g_deg_u);
    cudaGetSymbolAddress(&p_deg_i, g_deg_i);
    cudaGetSymbolAddress(&p_uf16, g_uf16);
    cudaGetSymbolAddress(&p_if16, g_if16);
    {
        void* tmp;
        cudaGetSymbolAddress(&tmp, g_hu16);
        for (int k = 0; k < 3; ++k) p_hu[k] = (char*)tmp + (size_t)k * NUx * 32 * sizeof(__half2);
        cudaGetSymbolAddress(&tmp, g_hi16);
        for (int k = 0; k < 3; ++k) p_hi[k] = (char*)tmp + (size_t)k * NIx * 32 * sizeof(__half2);
    }

    // ---- CSR build + fp16 input staging (fused launches) ----
    cudaMemsetAsync(p_deg_u, 0, NUx * sizeof(int));
    cudaMemsetAsync(p_deg_i, 0, NIx * sizeof(int));
    k_prep<<<CVTB + DEGB, 256>>>(uf, itf, eu, ei);
    k_scan_blocks2<<<SCANB_U + SCANB_I, SB>>>();
    k_scan_small2<<<2, 128>>>();
    k_scan_add2<<<SCANB_U + SCANB_I, SB>>>();
    k_fill<<<(Ex + 255) / 256, 256>>>(eu, ei);

    const unsigned npairs = (NUx + NIx) / 2;
    const unsigned gagg = (unsigned)(((size_t)npairs * 32 + 255) / 256);

    // ---- 3 propagation layers (both directions merged per launch) ----
    k_agg<<<gagg, 256>>>((const __half2*)p_uf16, (const __half2*)p_if16,
                         (__half2*)p_hu[0], (__half2*)p_hi[0]);
    k_agg<<<gagg, 256>>>((const __half2*)p_hu[0], (const __half2*)p_hi[0],
                         (__half2*)p_hu[1], (__half2*)p_hi[1]);
    k_agg<<<gagg, 256>>>((const __half2*)p_hu[1], (const __half2*)p_hi[1],
                         (__half2*)p_hu[2], (__half2*)p_hi[2]);

    // ---- output gather (e computed on the fly) ----
    k_out<<<(3 * Bx * 16 + 255) / 256, 256>>>(uf, itf, usr, pos, neg, out);
}

// round 11
// speedup vs baseline: 1.5490x; 1.0011x over previous
#include <cuda_runtime.h>
#include <cuda_fp16.h>

#define NUx 200000
#define NIx 100000
#define Dx  64
#define Ex  2000000
#define Bx  8192
#define EPSx 1e-12f

#define SB 256
#define SI 8                 // 2048 elements per scan block
#define NW (SB/32)

#define CVTB (((NUx + NIx) * 32 + 255) / 256)   // blocks for cvt part of prep
#define DEGB ((Ex + 255) / 256)                 // blocks for deg part of prep
#define SCANB_U ((NUx + SB * SI - 1) / (SB * SI))   // 98
#define SCANB_I ((NIx + SB * SI - 1) / (SB * SI))   // 49

// ---- static device scratch (no allocation allowed) ----
__device__ int g_deg[NUx + NIx];     // users [0,NU), items [NU,NU+NI)
__device__ int g_off_u[NUx];
__device__ int g_off_i[NIx];
__device__ int g_cur_u[NUx];
__device__ int g_cur_i[NIx];
__device__ int g_bsum_u[128];
__device__ int g_bsum_i[128];
__device__ __align__(16) int2 g_adj_u[Ex];   // per-user: (item, norm_e)
__device__ __align__(16) int2 g_adj_i[Ex];   // per-item: (user, norm_e)

// fp16 feature storage: rows of 32 half2 (64 halves = 128B)
__device__ __align__(256) __half2 g_uf16[(size_t)NUx * 32];
__device__ __align__(256) __half2 g_if16[(size_t)NIx * 32];
__device__ __align__(256) __half2 g_hu16[3][(size_t)NUx * 32];
__device__ __align__(256) __half2 g_hi16[3][(size_t)NIx * 32];

// ---- fused: fp16 input conversion + degree histogram (block-range split) ----
__global__ void k_prep(const float* __restrict__ uf, const float* __restrict__ itf,
                       const int* __restrict__ eu, const int* __restrict__ ei) {
    if (blockIdx.x < CVTB) {
        int t = blockIdx.x * blockDim.x + threadIdx.x;
        if (t < NUx * 32) {
            float2 f = ((const float2*)uf)[t];
            g_uf16[t] = __float22half2_rn(f);
        } else if (t < (NUx + NIx) * 32) {
            int s = t - NUx * 32;
            float2 f = ((const float2*)itf)[s];
            g_if16[s] = __float22half2_rn(f);
        }
    } else {
        int e = (blockIdx.x - CVTB) * blockDim.x + threadIdx.x;
        if (e < Ex) {
            atomicAdd(&g_deg[eu[e]], 1);
            atomicAdd(&g_deg[NUx + ei[e]], 1);
        }
    }
}

// ---- exclusive scan stage 1 for BOTH segments in one launch ----
__global__ void k_scan_blocks2() {
    const int* in; int* out; int* bsum; int n; int blk;
    if (blockIdx.x < SCANB_U) {
        in = g_deg; out = g_off_u; bsum = g_bsum_u; n = NUx; blk = blockIdx.x;
    } else {
        in = g_deg + NUx; out = g_off_i; bsum = g_bsum_i; n = NIx; blk = blockIdx.x - SCANB_U;
    }
    __shared__ int warp_tot[NW];
    int lane = threadIdx.x & 31, wid = threadIdx.x >> 5;
    int base = blk * (SB * SI) + threadIdx.x * SI;

    int v[SI];
    int s = 0;
    #pragma unroll
    for (int k = 0; k < SI; ++k) {
        int idx = base + k;
        v[k] = (idx < n) ? in[idx] : 0;
        s += v[k];
    }
    int ps = s;
    #pragma unroll
    for (int o = 1; o < 32; o <<= 1) {
        int t = __shfl_up_sync(0xffffffffu, ps, o);
        if (lane >= o) ps += t;
    }
    if (lane == 31) warp_tot[wid] = ps;
    __syncthreads();
    if (wid == 0) {
        int wt = (lane < NW) ? warp_tot[lane] : 0;
        int wps = wt;
        #pragma unroll
        for (int o = 1; o < NW; o <<= 1) {
            int t = __shfl_up_sync(0xffffffffu, wps, o);
            if (lane >= o) wps += t;
        }
        if (lane < NW) warp_tot[lane] = wps - wt;
    }
    __syncthreads();
    int excl = warp_tot[wid] + (ps - s);
    int run = excl;
    #pragma unroll
    for (int k = 0; k < SI; ++k) {
        int idx = base + k;
        if (idx < n) out[idx] = run;
        run += v[k];
    }
    if (threadIdx.x == SB - 1) bsum[blk] = excl + s;
}

// ---- scan stage 2+3 fused: each block self-computes its bsum prefix ----
__global__ void k_scan_add2() {
    int* out; int* cur; const int* bsum; int n; int blk;
    if (blockIdx.x < SCANB_U) {
        out = g_off_u; cur = g_cur_u; bsum = g_bsum_u; n = NUx; blk = blockIdx.x;
    } else {
        out = g_off_i; cur = g_cur_i; bsum = g_bsum_i; n = NIx; blk = blockIdx.x - SCANB_U;
    }
    // reduce bsum[0..blk) cooperatively (<=98 values, L2-hot)
    __shared__ int ssum[NW];
    int part = 0;
    for (int k = threadIdx.x; k < blk; k += SB) part += bsum[k];
    #pragma unroll
    for (int o = 16; o; o >>= 1) part += __shfl_xor_sync(0xffffffffu, part, o);
    if ((threadIdx.x & 31) == 0) ssum[threadIdx.x >> 5] = part;
    __syncthreads();
    int add = 0;
    #pragma unroll
    for (int k = 0; k < NW; ++k) add += ssum[k];

    int base = blk * (SB * SI) + threadIdx.x * SI;
    #pragma unroll
    for (int k = 0; k < SI; ++k) {
        int idx = base + k;
        if (idx < n) {
            int val = out[idx] + add;
            out[idx] = val;
            cur[idx] = val;
        }
    }
}

// ---- counting-sort fill of both adjacency lists + per-edge norm ----
__global__ void k_fill(const int* __restrict__ eu, const int* __restrict__ ei) {
    int e = blockIdx.x * blockDim.x + threadIdx.x;
    if (e >= Ex) return;
    int u = eu[e], i = ei[e];
    float w = rsqrtf((float)(g_deg[u] * g_deg[NUx + i]));
    int wb = __float_as_int(w);
    int pu = atomicAdd(&g_cur_u[u], 1);
    g_adj_u[pu] = make_int2(i, wb);
    int pi = atomicAdd(&g_cur_i[i], 1);
    g_adj_i[pi] = make_int2(u, wb);
}

// ---- merged both-direction gather-aggregate + fused L2-normalize ----
// ONE WARP PER TWO CONSECUTIVE DEST ROWS (proven fastest shape, R8/R10).
__global__ void k_agg(const __half2* __restrict__ srcU,
                      const __half2* __restrict__ srcI,
                      __half2* __restrict__ houtU,
                      __half2* __restrict__ houtI) {
    __shared__ int2 sh[NW][32];
    int gw = (blockIdx.x * blockDim.x + threadIdx.x) >> 5;   // pair index
    int lane = threadIdx.x & 31;
    int wid = threadIdx.x >> 5;
    const int PI = NIx / 2, PU = NUx / 2;
    if (gw >= PI + PU) return;

    const __half2* src;
    __half2* hout;
    const int2* adj;
    const int* off;
    int row0, nrows;
    if (gw < PI) {
        row0 = gw * 2; nrows = NIx;
        src = srcU; hout = houtI; adj = g_adj_i; off = g_off_i;
    } else {
        row0 = (gw - PI) * 2; nrows = NUx;
        src = srcI; hout = houtU; adj = g_adj_u; off = g_off_u;
    }

    int beg = off[row0];
    int mid = off[row0 + 1];
    int end = (row0 + 2 < nrows) ? off[row0 + 2] : Ex;

    float2 acc0 = make_float2(0.f, 0.f);
    float2 acc1 = make_float2(0.f, 0.f);

    for (int p = beg; p < end; p += 32) {
        int idx = p + lane;
        if (idx < end) sh[wid][lane] = adj[idx];
        __syncwarp();
        int c = min(end - p, 32);
        #pragma unroll 4
        for (int j = 0; j < c; ++j) {
            int2 a = sh[wid][j];
            float2 v = __half22float2(src[(size_t)a.x * 32 + lane]);
            float w = __int_as_float(a.y);
            if (p + j < mid) {                 // warp-uniform branch
                acc0.x += w * v.x; acc0.y += w * v.y;
            } else {
                acc1.x += w * v.x; acc1.y += w * v.y;
            }
        }
        __syncwarp();
    }

    float s0 = acc0.x * acc0.x + acc0.y * acc0.y;
    float s1 = acc1.x * acc1.x + acc1.y * acc1.y;
    #pragma unroll
    for (int o = 16; o; o >>= 1) {
        s0 += __shfl_xor_sync(0xffffffffu, s0, o);
        s1 += __shfl_xor_sync(0xffffffffu, s1, o);
    }
    float inv0 = 1.0f / fmaxf(sqrtf(s0), EPSx);
    float inv1 = 1.0f / fmaxf(sqrtf(s1), EPSx);

    hout[(size_t)row0 * 32 + lane] =
        __float22half2_rn(make_float2(acc0.x * inv0, acc0.y * inv0));
    hout[(size_t)(row0 + 1) * 32 + lane] =
        __float22half2_rn(make_float2(acc1.x * inv1, acc1.y * inv1));
}

// ---- final gather: e = f + h0 + h1/2 + h2/3 at sampled rows ----
__global__ void k_out(const float* __restrict__ uf, const float* __restrict__ itf,
                      const int* __restrict__ users, const int* __restrict__ pos,
                      const int* __restrict__ neg, float* __restrict__ out) {
    unsigned t = blockIdx.x * blockDim.x + threadIdx.x;
    unsigned r = t >> 4;
    unsigned lane = t & 15u;          // 16 lanes x 4 cols = 64
    if (r >= 3u * Bx) return;
    unsigned grp = r / Bx, idx = r % Bx;

    const float* base;
    const __half2 *h0, *h1, *h2;
    size_t row;
    if (grp == 0) {
        row = (size_t)users[idx];
        base = uf + row * Dx;
        h0 = g_hu16[0] + row * 32; h1 = g_hu16[1] + row * 32; h2 = g_hu16[2] + row * 32;
    } else {
        row = (size_t)((grp == 1) ? pos[idx] : neg[idx]);
        base = itf + row * Dx;
        h0 = g_hi16[0] + row * 32; h1 = g_hi16[1] + row * 32; h2 = g_hi16[2] + row * 32;
    }

    float4 f = *(const float4*)(base + lane * 4);
    float2 a0 = __half22float2(h0[lane * 2]), b0 = __half22float2(h0[lane * 2 + 1]);
    float2 a1 = __half22float2(h1[lane * 2]), b1 = __half22float2(h1[lane * 2 + 1]);
    float2 a2 = __half22float2(h2[lane * 2]), b2 = __half22float2(h2[lane * 2 + 1]);

    const float c1 = 0.5f, c2 = 1.0f / 3.0f;
    f.x += a0.x + c1 * a1.x + c2 * a2.x;
    f.y += a0.y + c1 * a1.y + c2 * a2.y;
    f.z += b0.x + c1 * b1.x + c2 * b2.x;
    f.w += b0.y + c1 * b1.y + c2 * b2.y;

    *(float4*)(out + (size_t)r * Dx + lane * 4) = f;
}

extern "C" void kernel_launch(void* const* d_in, const int* in_sizes, int n_in,
                              void* d_out, int out_size) {
    const float* uf  = (const float*)d_in[0];
    const float* itf = (const float*)d_in[1];
    const int*   eu  = (const int*)d_in[2];
    const int*   ei  = (const int*)d_in[3];
    const int*   usr = (const int*)d_in[4];
    const int*   pos = (const int*)d_in[5];
    const int*   neg = (const int*)d_in[6];
    float* out = (float*)d_out;

    void *p_deg;
    void *p_uf16, *p_if16, *p_hu[3], *p_hi[3];
    cudaGetSymbolAddress(&p_deg, g_deg);
    cudaGetSymbolAddress(&p_uf16, g_uf16);
    cudaGetSymbolAddress(&p_if16, g_if16);
    {
        void* tmp;
        cudaGetSymbolAddress(&tmp, g_hu16);
        for (int k = 0; k < 3; ++k) p_hu[k] = (char*)tmp + (size_t)k * NUx * 32 * sizeof(__half2);
        cudaGetSymbolAddress(&tmp, g_hi16);
        for (int k = 0; k < 3; ++k) p_hi[k] = (char*)tmp + (size_t)k * NIx * 32 * sizeof(__half2);
    }

    // ---- CSR build + fp16 input staging (5 launches before agg) ----
    cudaMemsetAsync(p_deg, 0, (NUx + NIx) * sizeof(int));            // #1
    k_prep<<<CVTB + DEGB, 256>>>(uf, itf, eu, ei);                   // #2
    k_scan_blocks2<<<SCANB_U + SCANB_I, SB>>>();                     // #3
    k_scan_add2<<<SCANB_U + SCANB_I, SB>>>();                        // #4
    k_fill<<<(Ex + 255) / 256, 256>>>(eu, ei);                       // #5

    const unsigned npairs = (NUx + NIx) / 2;
    const unsigned gagg = (unsigned)(((size_t)npairs * 32 + 255) / 256);

    // ---- 3 propagation layers (launch #6 = agg layer 0 → ncu target) ----
    k_agg<<<gagg, 256>>>((const __half2*)p_uf16, (const __half2*)p_if16,
                         (__half2*)p_hu[0], (__half2*)p_hi[0]);
    k_agg<<<gagg, 256>>>((const __half2*)p_hu[0], (const __half2*)p_hi[0],
                         (__half2*)p_hu[1], (__half2*)p_hi[1]);
    k_agg<<<gagg, 256>>>((const __half2*)p_hu[1], (const __half2*)p_hi[1],
                         (__half2*)p_hu[2], (__half2*)p_hi[2]);

    // ---- output gather (e computed on the fly) ----
    k_out<<<(3 * Bx * 16 + 255) / 256, 256>>>(uf, itf, usr, pos, neg, out);
}

// round 12
// speedup vs baseline: 1.5691x; 1.0130x over previous
#include <cuda_runtime.h>
#include <cuda_fp16.h>

#define NUx 200000
#define NIx 100000
#define Dx  64
#define Ex  2000000
#define Bx  8192
#define EPSx 1e-12f

#define SB 256
#define SI 8                 // 2048 elements per scan block
#define NW (SB/32)

#define CVTB (((NUx + NIx) * 16 + 255) / 256)   // float4-wide cvt: 4.8M threads
#define DEGB ((Ex / 4 + 255) / 256)             // 4 edges per thread
#define SCANB_U ((NUx + SB * SI - 1) / (SB * SI))   // 98
#define SCANB_I ((NIx + SB * SI - 1) / (SB * SI))   // 49

// ---- static device scratch (no allocation allowed) ----
// g_deg is zero at kernel_launch entry: static-init zero on first run,
// re-zeroed by k_out at the end of every run (k_fill is its last reader).
__device__ int g_deg[NUx + NIx];     // users [0,NU), items [NU,NU+NI)
__device__ int g_off_u[NUx];
__device__ int g_off_i[NIx];
__device__ int g_cur_u[NUx];
__device__ int g_cur_i[NIx];
__device__ int g_bsum_u[128];
__device__ int g_bsum_i[128];
__device__ __align__(16) int2 g_adj_u[Ex];   // per-user: (item, norm_e)
__device__ __align__(16) int2 g_adj_i[Ex];   // per-item: (user, norm_e)

// fp16 feature storage: rows of 32 half2 (64 halves = 128B)
__device__ __align__(256) __half2 g_uf16[(size_t)NUx * 32];
__device__ __align__(256) __half2 g_if16[(size_t)NIx * 32];
__device__ __align__(256) __half2 g_hu16[3][(size_t)NUx * 32];
__device__ __align__(256) __half2 g_hi16[3][(size_t)NIx * 32];

// ---- fused: fp16 input conversion (float4-wide) + degree histogram ----
__global__ void k_prep(const float* __restrict__ uf, const float* __restrict__ itf,
                       const int* __restrict__ eu, const int* __restrict__ ei) {
    if (blockIdx.x < CVTB) {
        int t = blockIdx.x * blockDim.x + threadIdx.x;   // one float4 = 2 half2
        if (t < NUx * 16) {
            float4 f = ((const float4*)uf)[t];
            g_uf16[t * 2]     = __float22half2_rn(make_float2(f.x, f.y));
            g_uf16[t * 2 + 1] = __float22half2_rn(make_float2(f.z, f.w));
        } else if (t < (NUx + NIx) * 16) {
            int s = t - NUx * 16;
            float4 f = ((const float4*)itf)[s];
            g_if16[s * 2]     = __float22half2_rn(make_float2(f.x, f.y));
            g_if16[s * 2 + 1] = __float22half2_rn(make_float2(f.z, f.w));
        }
    } else {
        int e4 = (blockIdx.x - CVTB) * blockDim.x + threadIdx.x;
        if (e4 < Ex / 4) {
            int4 u4 = ((const int4*)eu)[e4];
            int4 i4 = ((const int4*)ei)[e4];
            atomicAdd(&g_deg[u4.x], 1);
            atomicAdd(&g_deg[u4.y], 1);
            atomicAdd(&g_deg[u4.z], 1);
            atomicAdd(&g_deg[u4.w], 1);
            atomicAdd(&g_deg[NUx + i4.x], 1);
            atomicAdd(&g_deg[NUx + i4.y], 1);
            atomicAdd(&g_deg[NUx + i4.z], 1);
            atomicAdd(&g_deg[NUx + i4.w], 1);
        }
    }
}

// ---- exclusive scan stage 1 for BOTH segments in one launch ----
__global__ void k_scan_blocks2() {
    const int* in; int* out; int* bsum; int n; int blk;
    if (blockIdx.x < SCANB_U) {
        in = g_deg; out = g_off_u; bsum = g_bsum_u; n = NUx; blk = blockIdx.x;
    } else {
        in = g_deg + NUx; out = g_off_i; bsum = g_bsum_i; n = NIx; blk = blockIdx.x - SCANB_U;
    }
    __shared__ int warp_tot[NW];
    int lane = threadIdx.x & 31, wid = threadIdx.x >> 5;
    int base = blk * (SB * SI) + threadIdx.x * SI;

    int v[SI];
    int s = 0;
    #pragma unroll
    for (int k = 0; k < SI; ++k) {
        int idx = base + k;
        v[k] = (idx < n) ? in[idx] : 0;
        s += v[k];
    }
    int ps = s;
    #pragma unroll
    for (int o = 1; o < 32; o <<= 1) {
        int t = __shfl_up_sync(0xffffffffu, ps, o);
        if (lane >= o) ps += t;
    }
    if (lane == 31) warp_tot[wid] = ps;
    __syncthreads();
    if (wid == 0) {
        int wt = (lane < NW) ? warp_tot[lane] : 0;
        int wps = wt;
        #pragma unroll
        for (int o = 1; o < NW; o <<= 1) {
            int t = __shfl_up_sync(0xffffffffu, wps, o);
            if (lane >= o) wps += t;
        }
        if (lane < NW) warp_tot[lane] = wps - wt;
    }
    __syncthreads();
    int excl = warp_tot[wid] + (ps - s);
    int run = excl;
    #pragma unroll
    for (int k = 0; k < SI; ++k) {
        int idx = base + k;
        if (idx < n) out[idx] = run;
        run += v[k];
    }
    if (threadIdx.x == SB - 1) bsum[blk] = excl + s;
}

// ---- scan stage 2+3 fused: each block self-computes its bsum prefix ----
__global__ void k_scan_add2() {
    int* out; int* cur; const int* bsum; int n; int blk;
    if (blockIdx.x < SCANB_U) {
        out = g_off_u; cur = g_cur_u; bsum = g_bsum_u; n = NUx; blk = blockIdx.x;
    } else {
        out = g_off_i; cur = g_cur_i; bsum = g_bsum_i; n = NIx; blk = blockIdx.x - SCANB_U;
    }
    __shared__ int ssum[NW];
    int part = 0;
    for (int k = threadIdx.x; k < blk; k += SB) part += bsum[k];
    #pragma unroll
    for (int o = 16; o; o >>= 1) part += __shfl_xor_sync(0xffffffffu, part, o);
    if ((threadIdx.x & 31) == 0) ssum[threadIdx.x >> 5] = part;
    __syncthreads();
    int add = 0;
    #pragma unroll
    for (int k = 0; k < NW; ++k) add += ssum[k];

    int base = blk * (SB * SI) + threadIdx.x * SI;
    #pragma unroll
    for (int k = 0; k < SI; ++k) {
        int idx = base + k;
        if (idx < n) {
            int val = out[idx] + add;
            out[idx] = val;
            cur[idx] = val;
        }
    }
}

// ---- counting-sort fill of both adjacency lists + per-edge norm ----
__global__ void k_fill(const int* __restrict__ eu, const int* __restrict__ ei) {
    int e = blockIdx.x * blockDim.x + threadIdx.x;
    if (e >= Ex) return;
    int u = eu[e], i = ei[e];
    float w = rsqrtf((float)(g_deg[u] * g_deg[NUx + i]));
    int wb = __float_as_int(w);
    int pu = atomicAdd(&g_cur_u[u], 1);
    g_adj_u[pu] = make_int2(i, wb);
    int pi = atomicAdd(&g_cur_i[i], 1);
    g_adj_i[pi] = make_int2(u, wb);
}

// ---- merged both-direction gather-aggregate + fused L2-normalize ----
// ONE WARP PER TWO CONSECUTIVE DEST ROWS (proven fastest shape, R8/R10).
__global__ void k_agg(const __half2* __restrict__ srcU,
                      const __half2* __restrict__ srcI,
                      __half2* __restrict__ houtU,
                      __half2* __restrict__ houtI) {
    __shared__ int2 sh[NW][32];
    int gw = (blockIdx.x * blockDim.x + threadIdx.x) >> 5;   // pair index
    int lane = threadIdx.x & 31;
    int wid = threadIdx.x >> 5;
    const int PI = NIx / 2, PU = NUx / 2;
    if (gw >= PI + PU) return;

    const __half2* src;
    __half2* hout;
    const int2* adj;
    const int* off;
    int row0, nrows;
    if (gw < PI) {
        row0 = gw * 2; nrows = NIx;
        src = srcU; hout = houtI; adj = g_adj_i; off = g_off_i;
    } else {
        row0 = (gw - PI) * 2; nrows = NUx;
        src = srcI; hout = houtU; adj = g_adj_u; off = g_off_u;
    }

    int beg = off[row0];
    int mid = off[row0 + 1];
    int end = (row0 + 2 < nrows) ? off[row0 + 2] : Ex;

    float2 acc0 = make_float2(0.f, 0.f);
    float2 acc1 = make_float2(0.f, 0.f);

    for (int p = beg; p < end; p += 32) {
        int idx = p + lane;
        if (idx < end) sh[wid][lane] = adj[idx];
        __syncwarp();
        int c = min(end - p, 32);
        #pragma unroll 4
        for (int j = 0; j < c; ++j) {
            int2 a = sh[wid][j];
            float2 v = __half22float2(src[(size_t)a.x * 32 + lane]);
            float w = __int_as_float(a.y);
            if (p + j < mid) {                 // warp-uniform branch
                acc0.x += w * v.x; acc0.y += w * v.y;
            } else {
                acc1.x += w * v.x; acc1.y += w * v.y;
            }
        }
        __syncwarp();
    }

    float s0 = acc0.x * acc0.x + acc0.y * acc0.y;
    float s1 = acc1.x * acc1.x + acc1.y * acc1.y;
    #pragma unroll
    for (int o = 16; o; o >>= 1) {
        s0 += __shfl_xor_sync(0xffffffffu, s0, o);
        s1 += __shfl_xor_sync(0xffffffffu, s1, o);
    }
    float inv0 = 1.0f / fmaxf(sqrtf(s0), EPSx);
    float inv1 = 1.0f / fmaxf(sqrtf(s1), EPSx);

    hout[(size_t)row0 * 32 + lane] =
        __float22half2_rn(make_float2(acc0.x * inv0, acc0.y * inv0));
    hout[(size_t)(row0 + 1) * 32 + lane] =
        __float22half2_rn(make_float2(acc1.x * inv1, acc1.y * inv1));
}

// ---- final gather: e = f + h0 + h1/2 + h2/3 + deg re-zero for next run ----
__global__ void k_out(const float* __restrict__ uf, const float* __restrict__ itf,
                      const int* __restrict__ users, const int* __restrict__ pos,
                      const int* __restrict__ neg, float* __restrict__ out) {
    unsigned t = blockIdx.x * blockDim.x + threadIdx.x;
    if (t < NUx + NIx) g_deg[t] = 0;    // restore invariant for next replay
    unsigned r = t >> 4;
    unsigned lane = t & 15u;            // 16 lanes x 4 cols = 64
    if (r >= 3u * Bx) return;
    unsigned grp = r / Bx, idx = r % Bx;

    const float* base;
    const __half2 *h0, *h1, *h2;
    size_t row;
    if (grp == 0) {
        row = (size_t)users[idx];
        base = uf + row * Dx;
        h0 = g_hu16[0] + row * 32; h1 = g_hu16[1] + row * 32; h2 = g_hu16[2] + row * 32;
    } else {
        row = (size_t)((grp == 1) ? pos[idx] : neg[idx]);
        base = itf + row * Dx;
        h0 = g_hi16[0] + row * 32; h1 = g_hi16[1] + row * 32; h2 = g_hi16[2] + row * 32;
    }

    float4 f = *(const float4*)(base + lane * 4);
    float2 a0 = __half22float2(h0[lane * 2]), b0 = __half22float2(h0[lane * 2 + 1]);
    float2 a1 = __half22float2(h1[lane * 2]), b1 = __half22float2(h1[lane * 2 + 1]);
    float2 a2 = __half22float2(h2[lane * 2]), b2 = __half22float2(h2[lane * 2 + 1]);

    const float c1 = 0.5f, c2 = 1.0f / 3.0f;
    f.x += a0.x + c1 * a1.x + c2 * a2.x;
    f.y += a0.y + c1 * a1.y + c2 * a2.y;
    f.z += b0.x + c1 * b1.x + c2 * b2.x;
    f.w += b0.y + c1 * b1.y + c2 * b2.y;

    *(float4*)(out + (size_t)r * Dx + lane * 4) = f;
}

extern "C" void kernel_launch(void* const* d_in, const int* in_sizes, int n_in,
                              void* d_out, int out_size) {
    const float* uf  = (const float*)d_in[0];
    const float* itf = (const float*)d_in[1];
    const int*   eu  = (const int*)d_in[2];
    const int*   ei  = (const int*)d_in[3];
    const int*   usr = (const int*)d_in[4];
    const int*   pos = (const int*)d_in[5];
    const int*   neg = (const int*)d_in[6];
    float* out = (float*)d_out;

    void *p_uf16, *p_if16, *p_hu[3], *p_hi[3];
    cudaGetSymbolAddress(&p_uf16, g_uf16);
    cudaGetSymbolAddress(&p_if16, g_if16);
    {
        void* tmp;
        cudaGetSymbolAddress(&tmp, g_hu16);
        for (int k = 0; k < 3; ++k) p_hu[k] = (char*)tmp + (size_t)k * NUx * 32 * sizeof(__half2);
        cudaGetSymbolAddress(&tmp, g_hi16);
        for (int k = 0; k < 3; ++k) p_hi[k] = (char*)tmp + (size_t)k * NIx * 32 * sizeof(__half2);
    }

    // ---- CSR build + fp16 input staging (4 launches before agg) ----
    // g_deg is zero at entry (static init on run 1; k_out re-zeroes it each run)
    k_prep<<<CVTB + DEGB, 256>>>(uf, itf, eu, ei);                   // #1
    k_scan_blocks2<<<SCANB_U + SCANB_I, SB>>>();                     // #2
    k_scan_add2<<<SCANB_U + SCANB_I, SB>>>();                        // #3
    k_fill<<<(Ex + 255) / 256, 256>>>(eu, ei);                       // #4

    const unsigned npairs = (NUx + NIx) / 2;
    const unsigned gagg = (unsigned)(((size_t)npairs * 32 + 255) / 256);

    // ---- 3 propagation layers (launch #5 = agg layer 0 → ncu target) ----
    k_agg<<<gagg, 256>>>((const __half2*)p_uf16, (const __half2*)p_if16,
                         (__half2*)p_hu[0], (__half2*)p_hi[0]);
    k_agg<<<gagg, 256>>>((const __half2*)p_hu[0], (const __half2*)p_hi[0],
                         (__half2*)p_hu[1], (__half2*)p_hi[1]);
    k_agg<<<gagg, 256>>>((const __half2*)p_hu[1], (const __half2*)p_hi[1],
                         (__half2*)p_hu[2], (__half2*)p_hi[2]);

    // ---- output gather (e computed on the fly) + deg re-zero ----
    k_out<<<(3 * Bx * 16 + 255) / 256, 256>>>(uf, itf, usr, pos, neg, out);
}

// round 13
// speedup vs baseline: 1.6412x; 1.0459x over previous
#include <cuda_runtime.h>
#include <cuda_fp16.h>

#define NUx 200000
#define NIx 100000
#define Dx  64
#define Ex  2000000
#define Bx  8192
#define EPSx 1e-12f

#define SB 256
#define SI 8                 // 2048 elements per scan block
#define NW (SB/32)

#define FILLB ((Ex + 255) / 256)                    // fill part of cvtfill
#define CVTB  (((NUx + NIx) * 16 + 255) / 256)      // scaled-cvt part (float4-wide)
#define DEGB  ((Ex / 4 + 255) / 256)                // 4 edges per thread
#define SCANB_U ((NUx + SB * SI - 1) / (SB * SI))   // 98
#define SCANB_I ((NIx + SB * SI - 1) / (SB * SI))   // 49

// ---- static device scratch (no allocation allowed) ----
// g_deg is zero at kernel_launch entry: static-init zero on first run,
// re-zeroed by k_out at the end of every run.
__device__ int g_deg[NUx + NIx];     // users [0,NU), items [NU,NU+NI)
__device__ float g_rsd[NUx + NIx];   // rsqrt(max(deg,1))
__device__ int g_off_u[NUx];
__device__ int g_off_i[NIx];
__device__ int g_cur_u[NUx];
__device__ int g_cur_i[NIx];
__device__ int g_bsum_u[128];
__device__ int g_bsum_i[128];
__device__ int g_adj_u[Ex];          // per-user neighbor items (ids only)
__device__ int g_adj_i[Ex];          // per-item neighbor users (ids only)

// fp16 PRE-SCALED feature storage (rows of 32 half2 = 128B):
// stored value = rsd[node] * feature (the gather-side weight is baked in).
__device__ __align__(256) __half2 g_uf16[(size_t)NUx * 32];
__device__ __align__(256) __half2 g_if16[(size_t)NIx * 32];
__device__ __align__(256) __half2 g_hu16[3][(size_t)NUx * 32];
__device__ __align__(256) __half2 g_hi16[3][(size_t)NIx * 32];

// ---- degree histogram (4 edges per thread) ----
__global__ void k_deg(const int* __restrict__ eu, const int* __restrict__ ei) {
    int e4 = blockIdx.x * blockDim.x + threadIdx.x;
    if (e4 < Ex / 4) {
        int4 u4 = ((const int4*)eu)[e4];
        int4 i4 = ((const int4*)ei)[e4];
        atomicAdd(&g_deg[u4.x], 1);
        atomicAdd(&g_deg[u4.y], 1);
        atomicAdd(&g_deg[u4.z], 1);
        atomicAdd(&g_deg[u4.w], 1);
        atomicAdd(&g_deg[NUx + i4.x], 1);
        atomicAdd(&g_deg[NUx + i4.y], 1);
        atomicAdd(&g_deg[NUx + i4.z], 1);
        atomicAdd(&g_deg[NUx + i4.w], 1);
    }
}

// ---- exclusive scan stage 1 for BOTH segments in one launch ----
__global__ void k_scan_blocks2() {
    const int* in; int* out; int* bsum; int n; int blk;
    if (blockIdx.x < SCANB_U) {
        in = g_deg; out = g_off_u; bsum = g_bsum_u; n = NUx; blk = blockIdx.x;
    } else {
        in = g_deg + NUx; out = g_off_i; bsum = g_bsum_i; n = NIx; blk = blockIdx.x - SCANB_U;
    }
    __shared__ int warp_tot[NW];
    int lane = threadIdx.x & 31, wid = threadIdx.x >> 5;
    int base = blk * (SB * SI) + threadIdx.x * SI;

    int v[SI];
    int s = 0;
    #pragma unroll
    for (int k = 0; k < SI; ++k) {
        int idx = base + k;
        v[k] = (idx < n) ? in[idx] : 0;
        s += v[k];
    }
    int ps = s;
    #pragma unroll
    for (int o = 1; o < 32; o <<= 1) {
        int t = __shfl_up_sync(0xffffffffu, ps, o);
        if (lane >= o) ps += t;
    }
    if (lane == 31) warp_tot[wid] = ps;
    __syncthreads();
    if (wid == 0) {
        int wt = (lane < NW) ? warp_tot[lane] : 0;
        int wps = wt;
        #pragma unroll
        for (int o = 1; o < NW; o <<= 1) {
            int t = __shfl_up_sync(0xffffffffu, wps, o);
            if (lane >= o) wps += t;
        }
        if (lane < NW) warp_tot[lane] = wps - wt;
    }
    __syncthreads();
    int excl = warp_tot[wid] + (ps - s);
    int run = excl;
    #pragma unroll
    for (int k = 0; k < SI; ++k) {
        int idx = base + k;
        if (idx < n) out[idx] = run;
        run += v[k];
    }
    if (threadIdx.x == SB - 1) bsum[blk] = excl + s;
}

// ---- scan stage 2+3 fused: each block self-computes its bsum prefix ----
__global__ void k_scan_add2() {
    int* out; int* cur; const int* bsum; int n; int blk;
    if (blockIdx.x < SCANB_U) {
        out = g_off_u; cur = g_cur_u; bsum = g_bsum_u; n = NUx; blk = blockIdx.x;
    } else {
        out = g_off_i; cur = g_cur_i; bsum = g_bsum_i; n = NIx; blk = blockIdx.x - SCANB_U;
    }
    __shared__ int ssum[NW];
    int part = 0;
    for (int k = threadIdx.x; k < blk; k += SB) part += bsum[k];
    #pragma unroll
    for (int o = 16; o; o >>= 1) part += __shfl_xor_sync(0xffffffffu, part, o);
    if ((threadIdx.x & 31) == 0) ssum[threadIdx.x >> 5] = part;
    __syncthreads();
    int add = 0;
    #pragma unroll
    for (int k = 0; k < NW; ++k) add += ssum[k];

    int base = blk * (SB * SI) + threadIdx.x * SI;
    #pragma unroll
    for (int k = 0; k < SI; ++k) {
        int idx = base + k;
        if (idx < n) {
            int val = out[idx] + add;
            out[idx] = val;
            cur[idx] = val;
        }
    }
}

// ---- fused: id-only counting-sort fill  +  rsd-scaled fp16 convert ----
// fill blocks first (long pole), cvt blocks after; both ready at this point
// (fill needs offsets, cvt needs deg) and run concurrently in one launch.
__global__ void k_cvtfill(const float* __restrict__ uf, const float* __restrict__ itf,
                          const int* __restrict__ eu, const int* __restrict__ ei) {
    if (blockIdx.x < FILLB) {
        int e = blockIdx.x * blockDim.x + threadIdx.x;
        if (e < Ex) {
            int u = eu[e], i = ei[e];
            int pu = atomicAdd(&g_cur_u[u], 1);
            g_adj_u[pu] = i;
            int pi = atomicAdd(&g_cur_i[i], 1);
            g_adj_i[pi] = u;
        }
    } else {
        int t = (blockIdx.x - FILLB) * blockDim.x + threadIdx.x;  // one float4
        if (t < NUx * 16) {
            int row = t >> 4;
            float rsd = rsqrtf((float)max(g_deg[row], 1));
            if ((t & 15) == 0) g_rsd[row] = rsd;
            float4 f = ((const float4*)uf)[t];
            g_uf16[t * 2]     = __float22half2_rn(make_float2(f.x * rsd, f.y * rsd));
            g_uf16[t * 2 + 1] = __float22half2_rn(make_float2(f.z * rsd, f.w * rsd));
        } else if (t < (NUx + NIx) * 16) {
            int s = t - NUx * 16;
            int row = s >> 4;
            float rsd = rsqrtf((float)max(g_deg[NUx + row], 1));
            if ((s & 15) == 0) g_rsd[NUx + row] = rsd;
            float4 f = ((const float4*)itf)[s];
            g_if16[s * 2]     = __float22half2_rn(make_float2(f.x * rsd, f.y * rsd));
            g_if16[s * 2 + 1] = __float22half2_rn(make_float2(f.z * rsd, f.w * rsd));
        }
    }
}

// ---- merged both-direction gather-aggregate + fused L2-normalize ----
// ONE WARP PER TWO CONSECUTIVE DEST ROWS (proven shape). Sources are
// pre-scaled by rsd_src, so the sum needs no weights; epilogue multiplies by
// rsd_dest so the OUTPUT is pre-scaled for the next layer's gather.
__global__ void k_agg(const __half2* __restrict__ srcU,
                      const __half2* __restrict__ srcI,
                      __half2* __restrict__ houtU,
                      __half2* __restrict__ houtI) {
    __shared__ int sh[NW][32];
    int gw = (blockIdx.x * blockDim.x + threadIdx.x) >> 5;   // pair index
    int lane = threadIdx.x & 31;
    int wid = threadIdx.x >> 5;
    const int PI = NIx / 2, PU = NUx / 2;
    if (gw >= PI + PU) return;

    const __half2* src;
    __half2* hout;
    const int* adj;
    const int* off;
    const float* rsd;
    int row0, nrows;
    if (gw < PI) {
        row0 = gw * 2; nrows = NIx;
        src = srcU; hout = houtI; adj = g_adj_i; off = g_off_i; rsd = g_rsd + NUx;
    } else {
        row0 = (gw - PI) * 2; nrows = NUx;
        src = srcI; hout = houtU; adj = g_adj_u; off = g_off_u; rsd = g_rsd;
    }

    int beg = off[row0];
    int mid = off[row0 + 1];
    int end = (row0 + 2 < nrows) ? off[row0 + 2] : Ex;

    float2 acc0 = make_float2(0.f, 0.f);
    float2 acc1 = make_float2(0.f, 0.f);

    for (int p = beg; p < end; p += 32) {
        int idx = p + lane;
        if (idx < end) sh[wid][lane] = adj[idx];
        __syncwarp();
        int c = min(end - p, 32);
        #pragma unroll 4
        for (int j = 0; j < c; ++j) {
            int id = sh[wid][j];
            float2 v = __half22float2(src[(size_t)id * 32 + lane]);
            if (p + j < mid) {                 // warp-uniform branch
                acc0.x += v.x; acc0.y += v.y;
            } else {
                acc1.x += v.x; acc1.y += v.y;
            }
        }
        __syncwarp();
    }

    float s0 = acc0.x * acc0.x + acc0.y * acc0.y;
    float s1 = acc1.x * acc1.x + acc1.y * acc1.y;
    #pragma unroll
    for (int o = 16; o; o >>= 1) {
        s0 += __shfl_xor_sync(0xffffffffu, s0, o);
        s1 += __shfl_xor_sync(0xffffffffu, s1, o);
    }
    float inv0 = rsd[row0]     / fmaxf(sqrtf(s0), EPSx);
    float inv1 = rsd[row0 + 1] / fmaxf(sqrtf(s1), EPSx);

    hout[(size_t)row0 * 32 + lane] =
        __float22half2_rn(make_float2(acc0.x * inv0, acc0.y * inv0));
    hout[(size_t)(row0 + 1) * 32 + lane] =
        __float22half2_rn(make_float2(acc1.x * inv1, acc1.y * inv1));
}

// ---- final gather: e = f + (h0 + h1/2 + h2/3)/rsd_dest;  deg re-zero ----
__global__ void k_out(const float* __restrict__ uf, const float* __restrict__ itf,
                      const int* __restrict__ users, const int* __restrict__ pos,
                      const int* __restrict__ neg, float* __restrict__ out) {
    unsigned t = blockIdx.x * blockDim.x + threadIdx.x;
    if (t < NUx + NIx) g_deg[t] = 0;    // restore invariant for next replay
    unsigned r = t >> 4;
    unsigned lane = t & 15u;            // 16 lanes x 4 cols = 64
    if (r >= 3u * Bx) return;
    unsigned grp = r / Bx, idx = r % Bx;

    const float* base;
    const __half2 *h0, *h1, *h2;
    float rsd;
    size_t row;
    if (grp == 0) {
        row = (size_t)users[idx];
        base = uf + row * Dx;
        rsd = g_rsd[row];
        h0 = g_hu16[0] + row * 32; h1 = g_hu16[1] + row * 32; h2 = g_hu16[2] + row * 32;
    } else {
        row = (size_t)((grp == 1) ? pos[idx] : neg[idx]);
        base = itf + row * Dx;
        rsd = g_rsd[NUx + row];
        h0 = g_hi16[0] + row * 32; h1 = g_hi16[1] + row * 32; h2 = g_hi16[2] + row * 32;
    }
    float un = 1.0f / rsd;   // unscale stored h' back to l2-normalized h

    float4 f = *(const float4*)(base + lane * 4);
    float2 a0 = __half22float2(h0[lane * 2]), b0 = __half22float2(h0[lane * 2 + 1]);
    float2 a1 = __half22float2(h1[lane * 2]), b1 = __half22float2(h1[lane * 2 + 1]);
    float2 a2 = __half22float2(h2[lane * 2]), b2 = __half22float2(h2[lane * 2 + 1]);

    const float c1 = 0.5f, c2 = 1.0f / 3.0f;
    f.x += (a0.x + c1 * a1.x + c2 * a2.x) * un;
    f.y += (a0.y + c1 * a1.y + c2 * a2.y) * un;
    f.z += (b0.x + c1 * b1.x + c2 * b2.x) * un;
    f.w += (b0.y + c1 * b1.y + c2 * b2.y) * un;

    *(float4*)(out + (size_t)r * Dx + lane * 4) = f;
}

extern "C" void kernel_launch(void* const* d_in, const int* in_sizes, int n_in,
                              void* d_out, int out_size) {
    const float* uf  = (const float*)d_in[0];
    const float* itf = (const float*)d_in[1];
    const int*   eu  = (const int*)d_in[2];
    const int*   ei  = (const int*)d_in[3];
    const int*   usr = (const int*)d_in[4];
    const int*   pos = (const int*)d_in[5];
    const int*   neg = (const int*)d_in[6];
    float* out = (float*)d_out;

    void *p_uf16, *p_if16, *p_hu[3], *p_hi[3];
    cudaGetSymbolAddress(&p_uf16, g_uf16);
    cudaGetSymbolAddress(&p_if16, g_if16);
    {
        void* tmp;
        cudaGetSymbolAddress(&tmp, g_hu16);
        for (int k = 0; k < 3; ++k) p_hu[k] = (char*)tmp + (size_t)k * NUx * 32 * sizeof(__half2);
        cudaGetSymbolAddress(&tmp, g_hi16);
        for (int k = 0; k < 3; ++k) p_hi[k] = (char*)tmp + (size_t)k * NIx * 32 * sizeof(__half2);
    }

    // ---- CSR build + pre-scaled fp16 staging (4 launches before agg) ----
    // g_deg is zero at entry (static init on run 1; k_out re-zeroes it)
    k_deg<<<DEGB, 256>>>(eu, ei);                                    // #1
    k_scan_blocks2<<<SCANB_U + SCANB_I, SB>>>();                     // #2
    k_scan_add2<<<SCANB_U + SCANB_I, SB>>>();                        // #3
    k_cvtfill<<<FILLB + CVTB, 256>>>(uf, itf, eu, ei);               // #4

    const unsigned npairs = (NUx + NIx) / 2;
    const unsigned gagg = (unsigned)(((size_t)npairs * 32 + 255) / 256);

    // ---- 3 propagation layers ----
    k_agg<<<gagg, 256>>>((const __half2*)p_uf16, (const __half2*)p_if16,
                         (__half2*)p_hu[0], (__half2*)p_hi[0]);
    k_agg<<<gagg, 256>>>((const __half2*)p_hu[0], (const __half2*)p_hi[0],
                         (__half2*)p_hu[1], (__half2*)p_hi[1]);
    k_agg<<<gagg, 256>>>((const __half2*)p_hu[1], (const __half2*)p_hi[1],
                         (__half2*)p_hu[2], (__half2*)p_hi[2]);

    // ---- output gather (unscale h', compute e on the fly) ----
    k_out<<<(3 * Bx * 16 + 255) / 256, 256>>>(uf, itf, usr, pos, neg, out);
}